// round 12
// baseline (speedup 1.0000x reference)
#include <cuda_runtime.h>
#include <cuda_fp16.h>
#include <cstdint>
#include <cstddef>

// ============================================================================
// GAT fusion, B=8192, N=12, D=256, SEL={0,3,6,9}.  sm_100 legacy-mma edition.
// Measured: f32-accum mma.sync ~52% of peak == half the f16-accum rate.
// This round: fp16x3 GEMMs issue pass hh with f32 accum, passes hl+lh with
// f16 accum (corrections ~1e-3 -> f16 error ~1e-6), folded at epilogue.
// K,Q fp16x3 (softmax-accurate); V,out fp16x1; Wh1/f1 fp16 intermediates.
// ============================================================================

#define BATCH   8192
#define NNODE   12
#define DIM     256
#define M_VK    (BATCH * NNODE)     // 98304
#define M_SEL   (BATCH * 4)         // 32768

// ---------------- scratch (device globals; no allocation) -------------------
__device__ __half g_hh[M_VK * DIM], g_hl[M_VK * DIM];    // h split (fp16)
__device__ __half g_Wh1[M_VK * DIM];                      // V output, fp16
__device__ float g_k1 [M_VK * DIM];
__device__ float g_q1 [M_SEL * DIM];
__device__ __half g_f1h[M_SEL * DIM];
__device__ float g_bc [DIM];
__device__ float g_Wc_part[8 * DIM * DIM];
__device__ __half g_Wv_h[DIM*DIM], g_Wv_l[DIM*DIM];
__device__ __half g_Wk_h[DIM*DIM], g_Wk_l[DIM*DIM];
__device__ __half g_Wq_h[DIM*DIM], g_Wq_l[DIM*DIM];
__device__ __half g_Wc_h[DIM*DIM];

// ---------------- helpers ----------------------------------------------------
__device__ __forceinline__ uint32_t smem_u32(const void* p) {
    return (uint32_t)__cvta_generic_to_shared(p);
}
__device__ __forceinline__ void ldmatrix_x4(uint32_t& r0, uint32_t& r1,
                                            uint32_t& r2, uint32_t& r3, uint32_t addr) {
    asm volatile("ldmatrix.sync.aligned.m8n8.x4.shared.b16 {%0,%1,%2,%3}, [%4];\n"
                 : "=r"(r0), "=r"(r1), "=r"(r2), "=r"(r3) : "r"(addr));
}
__device__ __forceinline__ void ldmatrix_x2(uint32_t& r0, uint32_t& r1, uint32_t addr) {
    asm volatile("ldmatrix.sync.aligned.m8n8.x2.shared.b16 {%0,%1}, [%2];\n"
                 : "=r"(r0), "=r"(r1) : "r"(addr));
}
// f32-accumulator mma (half-rate on sm_100)
__device__ __forceinline__ void mma_f16(float c[4],
                                        uint32_t a0, uint32_t a1, uint32_t a2, uint32_t a3,
                                        uint32_t b0, uint32_t b1) {
    asm volatile("mma.sync.aligned.m16n8k16.row.col.f32.f16.f16.f32 "
                 "{%0,%1,%2,%3}, {%4,%5,%6,%7}, {%8,%9}, {%0,%1,%2,%3};\n"
                 : "+f"(c[0]), "+f"(c[1]), "+f"(c[2]), "+f"(c[3])
                 : "r"(a0), "r"(a1), "r"(a2), "r"(a3), "r"(b0), "r"(b1));
}
// f16-accumulator mma (full-rate; used for small correction passes)
__device__ __forceinline__ void mma_f16h(uint32_t c[2],
                                         uint32_t a0, uint32_t a1, uint32_t a2, uint32_t a3,
                                         uint32_t b0, uint32_t b1) {
    asm volatile("mma.sync.aligned.m16n8k16.row.col.f16.f16.f16.f16 "
                 "{%0,%1}, {%2,%3,%4,%5}, {%6,%7}, {%0,%1};\n"
                 : "+r"(c[0]), "+r"(c[1])
                 : "r"(a0), "r"(a1), "r"(a2), "r"(a3), "r"(b0), "r"(b1));
}
__device__ __forceinline__ void cp16(uint32_t dst, const void* src) {
    asm volatile("cp.async.cg.shared.global [%0], [%1], 16;\n" :: "r"(dst), "l"(src));
}

// ---------------- prologue kernels -------------------------------------------
// all three attention weights in one launch: grid (256, 3)
__global__ void convert_w3_kernel(const float* __restrict__ s0, __half* __restrict__ h0, __half* __restrict__ l0,
                                  const float* __restrict__ s1, __half* __restrict__ h1, __half* __restrict__ l1,
                                  const float* __restrict__ s2, __half* __restrict__ h2, __half* __restrict__ l2) {
    const float* s; __half *hh, *ll;
    if (blockIdx.y == 0)      { s = s0; hh = h0; ll = l0; }
    else if (blockIdx.y == 1) { s = s1; hh = h1; ll = l1; }
    else                      { s = s2; hh = h2; ll = l2; }
    int i = blockIdx.x * 256 + threadIdx.x;
    float x = s[i];
    __half v = __float2half_rn(x);
    hh[i] = v;
    ll[i] = __float2half_rn(x - __half2float(v));
}

__global__ void convert_h_kernel(const float* __restrict__ src,
                                 __half* __restrict__ hi,
                                 __half* __restrict__ lo) {
    size_t i = ((size_t)blockIdx.x * 256 + threadIdx.x) * 8;
    float4 a = *(const float4*)(src + i);
    float4 b = *(const float4*)(src + i + 4);
    float x[8] = {a.x, a.y, a.z, a.w, b.x, b.y, b.z, b.w};
    uint32_t hw[4], lw[4];
    #pragma unroll
    for (int g = 0; g < 4; ++g) {
        __half h0 = __float2half_rn(x[2*g]);
        __half h1 = __float2half_rn(x[2*g+1]);
        __half l0 = __float2half_rn(x[2*g]   - __half2float(h0));
        __half l1 = __float2half_rn(x[2*g+1] - __half2float(h1));
        hw[g] = (uint32_t)__half_as_ushort(h0) | ((uint32_t)__half_as_ushort(h1) << 16);
        lw[g] = (uint32_t)__half_as_ushort(l0) | ((uint32_t)__half_as_ushort(l1) << 16);
    }
    *(uint4*)(hi + i) = make_uint4(hw[0], hw[1], hw[2], hw[3]);
    *(uint4*)(lo + i) = make_uint4(lw[0], lw[1], lw[2], lw[3]);
}

// ---- fold, stage 1: partial Wc over k-slices.  grid (32, 8), block 256 ------
__global__ void fold_part_kernel(const float* __restrict__ Wf,
                                 const float* __restrict__ Wo1,
                                 float* __restrict__ part) {
    __shared__ float sWf[8][32];
    const int t = threadIdx.x, o0 = blockIdx.x * 8, kz = blockIdx.y * 32;
    {
        int r = t >> 5, hh = t & 31;
        sWf[r][hh] = Wf[(o0 + r) * 256 + kz + hh];
    }
    __syncthreads();
    float acc[8] = {0,0,0,0,0,0,0,0};
    #pragma unroll
    for (int hh = 0; hh < 32; ++hh) {
        float x = Wo1[(kz + hh) * 256 + t];
        #pragma unroll
        for (int r = 0; r < 8; ++r) acc[r] = fmaf(sWf[r][hh], x, acc[r]);
    }
    #pragma unroll
    for (int r = 0; r < 8; ++r)
        part[((size_t)blockIdx.y << 16) + (o0 + r) * 256 + t] = acc[r];
}

// ---- fold, stage 2: reduce partials, fp16 hi, compute bc --------------------
__global__ void fold_reduce_kernel(const float* __restrict__ part,
                                   const float* __restrict__ Wf,
                                   const float* __restrict__ bo1,
                                   const float* __restrict__ bfb,
                                   __half* __restrict__ Wch,
                                   float* __restrict__ bc) {
    const int o = blockIdx.x, t = threadIdx.x;
    float v = 0.f;
    #pragma unroll
    for (int kz = 0; kz < 8; ++kz) v += part[((size_t)kz << 16) + o * 256 + t];
    Wch[o * 256 + t] = __float2half_rn(v);

    __shared__ float red[256];
    red[t] = Wf[o * 256 + t] * bo1[t];
    __syncthreads();
    #pragma unroll
    for (int s = 128; s > 0; s >>= 1) {
        if (t < s) red[t] += red[t + s];
        __syncthreads();
    }
    if (t == 0) bc[o] = red[0] + bfb[o];
}

// ---------------- pipelined mma.sync GEMM ------------------------------------
// C[M, 128 cols @ ncol0] = act(A @ W^T + bias). fp16 operands.
// PASSES=3: hh pass -> f32 accum; hl+lh passes -> f16 accum cc (corrections
// ~1e-3, f16 error negligible), folded at epilogue.  STAGES=2.
// PASSES=1: single hh pass, f32 accum.  STAGES=4.
// 82KB dynamic smem -> 2 CTAs/SM.  OUTH: epilogue stores __half.

template<int PASSES, bool GATHER, bool RELU, bool OUTH>
__global__ void __launch_bounds__(256, 2)
gemm2(const __half* __restrict__ Ah, const __half* __restrict__ Al,
      const __half* __restrict__ Wh, const __half* __restrict__ Wl,
      const float* __restrict__ bias, void* __restrict__ Cv,
      int Mtiles) {
    constexpr int ARR    = (PASSES == 3) ? 4 : 2;
    constexpr int NA     = (PASSES == 3) ? 2 : 1;
    constexpr int STAGES = (PASSES == 3) ? 2 : 4;
    constexpr uint32_t STG = ARR * 10240;

    extern __shared__ char smem[];
    const uint32_t sb = smem_u32(smem);
    float* sbias = (float*)(smem + STAGES * STG);
    const int t = threadIdx.x, lane = t & 31, wid = t >> 5;

    const int y   = blockIdx.x & 1;
    const int tb  = blockIdx.x >> 1;
    const int NTB = gridDim.x >> 1;
    const int ncol0 = y * 128;

    if (t < 128) sbias[t] = bias[ncol0 + t];

    int tiles = 0;
    for (int mt = tb; mt < Mtiles; mt += NTB) ++tiles;
    const int QS = tiles * 8;

    auto cp_stage = [&](int q) {
        const int lt = q >> 3, kt = q & 7;
        const int mt = tb + lt * NTB;
        const uint32_t db = sb + (uint32_t)(q & (STAGES - 1)) * STG;
        #pragma unroll
        for (int u = 0; u < ARR * 2; ++u) {
            const int s = t + (u << 8);
            const int id  = s >> 9;
            const int row = (s >> 2) & 127;
            const int seg = s & 3;
            const uint32_t dst = db + (uint32_t)(id * 10240 + row * 80 + seg * 16);
            const __half* src;
            if (id < NA) {
                int g = mt * 128 + row;
                if (GATHER) g = (g >> 2) * 12 + 3 * (g & 3);
                src = (id ? Al : Ah) + (size_t)g * 256 + kt * 32 + seg * 8;
            } else {
                src = ((id - NA) ? Wl : Wh) + (ncol0 + row) * 256 + kt * 32 + seg * 8;
            }
            cp16(dst, src);
        }
        asm volatile("cp.async.commit_group;\n" ::: "memory");
    };

    const int wm = (wid & 1) * 64;
    const int wn = (wid >> 1) * 32;
    const uint32_t aoff = (uint32_t)((wm + (lane & 15)) * 80 + ((lane >> 4) << 4));
    const uint32_t boff = (uint32_t)((lane & 7) * 80 + (((lane >> 3) & 1) << 4));

    float c[4][4][4];
    #pragma unroll
    for (int i = 0; i < 4; ++i)
        #pragma unroll
        for (int j = 0; j < 4; ++j)
            #pragma unroll
            for (int e = 0; e < 4; ++e) c[i][j][e] = 0.f;

    uint32_t cc[4][4][2];   // f16 correction accumulators (PASSES==3 only)
    if constexpr (PASSES == 3) {
        #pragma unroll
        for (int i = 0; i < 4; ++i)
            #pragma unroll
            for (int j = 0; j < 4; ++j)
                { cc[i][j][0] = 0u; cc[i][j][1] = 0u; }
    }

    const int npre = QS < (STAGES - 1) ? QS : (STAGES - 1);
    for (int q = 0; q < npre; ++q) cp_stage(q);

    for (int q = 0; q < QS; ++q) {
        const int kt = q & 7;
        if constexpr (STAGES == 2)
            asm volatile("cp.async.wait_group 0;\n" ::: "memory");
        else
            asm volatile("cp.async.wait_group 2;\n" ::: "memory");
        __syncthreads();
        if (q + STAGES - 1 < QS) cp_stage(q + STAGES - 1);

        {
            const uint32_t ab     = sb + (uint32_t)(q & (STAGES - 1)) * STG;
            const uint32_t albase = ab + 10240;
            const uint32_t bhbase = ab + NA * 10240;
            const uint32_t blbase = bhbase + 10240;
            #pragma unroll
            for (int ks = 0; ks < 32; ks += 16) {
                uint32_t rbh[4][2], rah[4][4];
                #pragma unroll
                for (int j = 0; j < 4; ++j) {
                    const uint32_t o = boff + (uint32_t)((wn + 8 * j) * 80 + ks * 2);
                    ldmatrix_x2(rbh[j][0], rbh[j][1], bhbase + o);
                }
                #pragma unroll
                for (int i = 0; i < 4; ++i) {
                    const uint32_t o = aoff + (uint32_t)(i * 16 * 80 + ks * 2);
                    ldmatrix_x4(rah[i][0], rah[i][1], rah[i][2], rah[i][3], ab + o);
                }
                // pass 1: hi*hi -> f32 accum (half rate, accuracy-critical)
                #pragma unroll
                for (int i = 0; i < 4; ++i)
                    #pragma unroll
                    for (int j = 0; j < 4; ++j)
                        mma_f16(c[i][j], rah[i][0], rah[i][1], rah[i][2], rah[i][3],
                                rbh[j][0], rbh[j][1]);
                if constexpr (PASSES == 3) {
                    {   // pass 2: hi*lo -> f16 accum (full rate)
                        uint32_t rbl[4][2];
                        #pragma unroll
                        for (int j = 0; j < 4; ++j) {
                            const uint32_t o = boff + (uint32_t)((wn + 8 * j) * 80 + ks * 2);
                            ldmatrix_x2(rbl[j][0], rbl[j][1], blbase + o);
                        }
                        #pragma unroll
                        for (int i = 0; i < 4; ++i)
                            #pragma unroll
                            for (int j = 0; j < 4; ++j)
                                mma_f16h(cc[i][j], rah[i][0], rah[i][1], rah[i][2], rah[i][3],
                                         rbl[j][0], rbl[j][1]);
                    }
                    {   // pass 3: lo*hi -> f16 accum (full rate)
                        uint32_t ral[4][4];
                        #pragma unroll
                        for (int i = 0; i < 4; ++i) {
                            const uint32_t o = aoff + (uint32_t)(i * 16 * 80 + ks * 2);
                            ldmatrix_x4(ral[i][0], ral[i][1], ral[i][2], ral[i][3], albase + o);
                        }
                        #pragma unroll
                        for (int i = 0; i < 4; ++i)
                            #pragma unroll
                            for (int j = 0; j < 4; ++j)
                                mma_f16h(cc[i][j], ral[i][0], ral[i][1], ral[i][2], ral[i][3],
                                         rbh[j][0], rbh[j][1]);
                    }
                }
            }
        }

        if (kt == 7) {
            const int mt = tb + (q >> 3) * NTB;
            const int gr = lane >> 2, gc = (lane & 3) * 2;
            const int mbase = mt * 128 + wm;
            #pragma unroll
            for (int i = 0; i < 4; ++i) {
                #pragma unroll
                for (int j = 0; j < 4; ++j) {
                    float v0 = c[i][j][0], v1 = c[i][j][1];
                    float v2 = c[i][j][2], v3 = c[i][j][3];
                    if constexpr (PASSES == 3) {
                        // fold f16 corrections: reg0 = {c0,c1}, reg1 = {c2,c3}
                        float2 lo = __half22float2(*(__half2*)&cc[i][j][0]);
                        float2 hi = __half22float2(*(__half2*)&cc[i][j][1]);
                        v0 += lo.x; v1 += lo.y; v2 += hi.x; v3 += hi.y;
                        cc[i][j][0] = 0u; cc[i][j][1] = 0u;
                    }
                    const int col = wn + 8 * j + gc;
                    const float b0v = sbias[col], b1v = sbias[col + 1];
                    v0 += b0v; v1 += b1v; v2 += b0v; v3 += b1v;
                    if (RELU) {
                        v0 = fmaxf(v0, 0.f); v1 = fmaxf(v1, 0.f);
                        v2 = fmaxf(v2, 0.f); v3 = fmaxf(v3, 0.f);
                    }
                    const int r0 = mbase + 16 * i + gr;
                    if constexpr (OUTH) {
                        __half* C = (__half*)Cv;
                        *(__half2*)&C[(size_t)r0 * 256 + ncol0 + col] =
                            __floats2half2_rn(v0, v1);
                        *(__half2*)&C[(size_t)(r0 + 8) * 256 + ncol0 + col] =
                            __floats2half2_rn(v2, v3);
                    } else {
                        float* C = (float*)Cv;
                        *(float2*)&C[(size_t)r0 * 256 + ncol0 + col]       = make_float2(v0, v1);
                        *(float2*)&C[(size_t)(r0 + 8) * 256 + ncol0 + col] = make_float2(v2, v3);
                    }
                    c[i][j][0] = 0.f; c[i][j][1] = 0.f;
                    c[i][j][2] = 0.f; c[i][j][3] = 0.f;
                }
            }
        }
    }
}

// ---------------- attention ---------------------------------------------------
// block = 128 thr = one batch; warp w -> sel row (node 3w).
// k1,q1 fp32; Wh1 fp16; f1 written fp16.
__global__ void __launch_bounds__(128)
attn_kernel(const float* __restrict__ q1, const float* __restrict__ k1,
            const __half* __restrict__ wh1, const float* __restrict__ label,
            const float* __restrict__ adj, __half* __restrict__ f1h) {
    __shared__ float  sk [NNODE * 256];
    __shared__ __half swh[NNODE * 256];
    __shared__ float  sq [4 * 256];
    __shared__ float  sadj[4 * NNODE];
    __shared__ float  slab[NNODE];

    const int b = blockIdx.x, t = threadIdx.x;

    const float4* k4 = (const float4*)(k1  + (size_t)b * NNODE * 256);
    const uint4*  w4 = (const uint4*)(wh1 + (size_t)b * NNODE * 256);
    const float4* q4 = (const float4*)(q1  + (size_t)b * 4 * 256);
    float4* dk = (float4*)sk;
    uint4*  dw = (uint4*)swh;
    float4* dq = (float4*)sq;
    #pragma unroll
    for (int u = 0; u < 6; ++u) dk[t + 128 * u] = k4[t + 128 * u];
    #pragma unroll
    for (int u = 0; u < 3; ++u) dw[t + 128 * u] = w4[t + 128 * u];
    #pragma unroll
    for (int u = 0; u < 2; ++u) dq[t + 128 * u] = q4[t + 128 * u];
    if (t < NNODE) slab[t] = label[b * NNODE + t];
    if (t < 4 * NNODE) {
        int i = t / NNODE, m = t % NNODE;
        sadj[t] = adj[(3 * i) * NNODE + m];
    }
    __syncthreads();

    const int w = t >> 5, l = t & 31;
    float qv[8];
    {
        const float4* qp = (const float4*)(sq + w * 256 + l * 8);
        float4 a = qp[0], bq_ = qp[1];
        qv[0]=a.x; qv[1]=a.y; qv[2]=a.z; qv[3]=a.w;
        qv[4]=bq_.x; qv[5]=bq_.y; qv[6]=bq_.z; qv[7]=bq_.w;
    }
    float s[NNODE];
    #pragma unroll
    for (int m = 0; m < NNODE; ++m) {
        const float4* kp = (const float4*)(sk + m * 256 + l * 8);
        float4 a = kp[0], bb = kp[1];
        s[m] = qv[0]*a.x + qv[1]*a.y + qv[2]*a.z + qv[3]*a.w
             + qv[4]*bb.x + qv[5]*bb.y + qv[6]*bb.z + qv[7]*bb.w;
    }
    #pragma unroll
    for (int m = 0; m < NNODE; ++m)
        #pragma unroll
        for (int off = 16; off > 0; off >>= 1)
            s[m] += __shfl_xor_sync(0xffffffffu, s[m], off);

    float mx = -3.0e38f;
    #pragma unroll
    for (int m = 0; m < NNODE; ++m) {
        float sm = (sadj[w * NNODE + m] > 0.5f) ? s[m] : -9.0e15f;
        s[m] = sm;
        mx = fmaxf(mx, sm);
    }
    float sum = 0.f;
    #pragma unroll
    for (int m = 0; m < NNODE; ++m) { float p = expf(s[m] - mx); s[m] = p; sum += p; }
    const float inv = 1.f / sum;
    #pragma unroll
    for (int m = 0; m < NNODE; ++m) s[m] = s[m] * inv * slab[m];

    float o[8] = {0,0,0,0,0,0,0,0};
    #pragma unroll
    for (int m = 0; m < NNODE; ++m) {
        const __half2* wp = (const __half2*)(swh + m * 256 + l * 8);
        float2 a0 = __half22float2(wp[0]);
        float2 a1 = __half22float2(wp[1]);
        float2 a2 = __half22float2(wp[2]);
        float2 a3 = __half22float2(wp[3]);
        float am = s[m];
        o[0] = fmaf(am, a0.x, o[0]); o[1] = fmaf(am, a0.y, o[1]);
        o[2] = fmaf(am, a1.x, o[2]); o[3] = fmaf(am, a1.y, o[3]);
        o[4] = fmaf(am, a2.x, o[4]); o[5] = fmaf(am, a2.y, o[5]);
        o[6] = fmaf(am, a3.x, o[6]); o[7] = fmaf(am, a3.y, o[7]);
    }
    uint32_t pk[4];
    #pragma unroll
    for (int g = 0; g < 4; ++g) {
        __half2 h2 = __floats2half2_rn(o[2*g], o[2*g+1]);
        pk[g] = *(uint32_t*)&h2;
    }
    const size_t idx = (size_t)(b * 4 + w) * 256 + l * 8;
    *(uint4*)(f1h + idx) = make_uint4(pk[0], pk[1], pk[2], pk[3]);
}

// ---------------- host launch -------------------------------------------------
extern "C" void kernel_launch(void* const* d_in, const int* in_sizes, int n_in,
                              void* d_out, int out_size) {
    const float* h     = (const float*)d_in[0];
    const float* adj   = (const float*)d_in[1];
    const float* label = (const float*)d_in[2];
    const float* Wv    = (const float*)d_in[3];
    const float* bv    = (const float*)d_in[4];
    const float* Wk    = (const float*)d_in[5];
    const float* bk    = (const float*)d_in[6];
    const float* Wq    = (const float*)d_in[7];
    const float* bq    = (const float*)d_in[8];
    const float* Wo1   = (const float*)d_in[9];
    const float* bo1   = (const float*)d_in[10];
    const float* Wf    = (const float*)d_in[11];
    const float* bf    = (const float*)d_in[12];
    float* out = (float*)d_out;

    float *p_k1, *p_q1, *p_bc, *p_part;
    __half *p_hh, *p_hl, *p_f1h, *p_Wh1;
    __half *p_Wvh, *p_Wvl, *p_Wkh, *p_Wkl, *p_Wqh, *p_Wql, *p_Wch;
    cudaGetSymbolAddress((void**)&p_Wh1, g_Wh1);
    cudaGetSymbolAddress((void**)&p_k1,  g_k1);
    cudaGetSymbolAddress((void**)&p_q1,  g_q1);
    cudaGetSymbolAddress((void**)&p_bc,  g_bc);
    cudaGetSymbolAddress((void**)&p_part, g_Wc_part);
    cudaGetSymbolAddress((void**)&p_hh,  g_hh);
    cudaGetSymbolAddress((void**)&p_hl,  g_hl);
    cudaGetSymbolAddress((void**)&p_f1h, g_f1h);
    cudaGetSymbolAddress((void**)&p_Wvh, g_Wv_h);
    cudaGetSymbolAddress((void**)&p_Wvl, g_Wv_l);
    cudaGetSymbolAddress((void**)&p_Wkh, g_Wk_h);
    cudaGetSymbolAddress((void**)&p_Wkl, g_Wk_l);
    cudaGetSymbolAddress((void**)&p_Wqh, g_Wq_h);
    cudaGetSymbolAddress((void**)&p_Wql, g_Wq_l);
    cudaGetSymbolAddress((void**)&p_Wch, g_Wc_h);

    const int SMEM3 = 2 * 40960 + 1024;   // 2-stage fp16x3 -> 2 CTAs/SM
    const int SMEM1 = 4 * 20480 + 1024;   // 4-stage fp16x1 -> 2 CTAs/SM
    cudaFuncSetAttribute(gemm2<3, false, true, false>,
                         cudaFuncAttributeMaxDynamicSharedMemorySize, SMEM3);
    cudaFuncSetAttribute(gemm2<3, true, true, false>,
                         cudaFuncAttributeMaxDynamicSharedMemorySize, SMEM3);
    cudaFuncSetAttribute(gemm2<1, false, true, true>,
                         cudaFuncAttributeMaxDynamicSharedMemorySize, SMEM1);
    cudaFuncSetAttribute(gemm2<1, false, false, false>,
                         cudaFuncAttributeMaxDynamicSharedMemorySize, SMEM1);

    // Launch order keeps the big K-GEMM at index 4 (the launch ncu captures).
    convert_h_kernel<<<12288, 256>>>(h, p_hh, p_hl);                       // 1
    convert_w3_kernel<<<dim3(256, 3), 256>>>(Wv, p_Wvh, p_Wvl,
                                             Wk, p_Wkh, p_Wkl,
                                             Wq, p_Wqh, p_Wql);            // 2
    fold_part_kernel<<<dim3(32, 8), 256>>>(Wf, Wo1, p_part);               // 3
    // K GEMM (fp16x3, f16-acc corrections): k1 = relu(h@Wk^T + bk)        // 4
    gemm2<3, false, true, false><<<296, 256, SMEM3>>>(
        p_hh, p_hl, p_Wkh, p_Wkl, bk, p_k1, M_VK / 128);
    // V GEMM (fp16x1): Wh1 = relu(h@Wv^T + bv), fp16 out                  // 5
    gemm2<1, false, true, true><<<296, 256, SMEM1>>>(
        p_hh, nullptr, p_Wvh, nullptr, bv, p_Wh1, M_VK / 128);
    // Q GEMM (fp16x3, gathered): q1 = relu(h_sel@Wq^T + bq), fp32 out     // 6
    gemm2<3, true, true, false><<<296, 256, SMEM3>>>(
        p_hh, p_hl, p_Wqh, p_Wql, bq, p_q1, M_SEL / 128);
    fold_reduce_kernel<<<256, 256>>>(p_part, Wf, bo1, bf, p_Wch, p_bc);    // 7
    attn_kernel<<<BATCH, 128>>>(p_q1, p_k1, p_Wh1, label, adj, p_f1h);     // 8
    // out GEMM (fp16x1) straight into d_out                               // 9
    gemm2<1, false, false, false><<<296, 256, SMEM1>>>(
        p_f1h, nullptr, p_Wch, nullptr, p_bc, out, M_SEL / 128);
}

// round 14
// speedup vs baseline: 1.0643x; 1.0643x over previous
#include <cuda_runtime.h>
#include <cuda_fp16.h>
#include <cstdint>
#include <cstddef>

// ============================================================================
// GAT fusion, B=8192, N=12, D=256, SEL={0,3,6,9}.  sm_100 legacy-mma edition.
// R12 falsified f16-accum speedup -> all passes back to f32 accum (R11 math).
// This round: K+Q+V fused into ONE persistent kernel (3584 flat jobs on 296
// CTAs -> 7% tail instead of 13-16% per-kernel tails; V jobs 1-pass, skip lo).
// K,Q fp16x3 (softmax-accurate); V,out fp16x1; Wh1/f1 fp16 intermediates.
// ============================================================================

#define BATCH   8192
#define NNODE   12
#define DIM     256
#define M_VK    (BATCH * NNODE)     // 98304
#define M_SEL   (BATCH * 4)         // 32768
#define NWORK   296                 // persistent workers (2 CTA/SM * 148)
#define NJOBS   3584                // K 1536 + Q 512 + V 1536

// ---------------- scratch (device globals; no allocation) -------------------
__device__ __half g_hh[M_VK * DIM], g_hl[M_VK * DIM];    // h split (fp16)
__device__ __half g_Wh1[M_VK * DIM];                      // V output, fp16
__device__ float g_k1 [M_VK * DIM];
__device__ float g_q1 [M_SEL * DIM];
__device__ __half g_f1h[M_SEL * DIM];
__device__ float g_bc [DIM];
__device__ float g_Wc_part[8 * DIM * DIM];
__device__ __half g_Wv_h[DIM*DIM], g_Wv_l[DIM*DIM];
__device__ __half g_Wk_h[DIM*DIM], g_Wk_l[DIM*DIM];
__device__ __half g_Wq_h[DIM*DIM], g_Wq_l[DIM*DIM];
__device__ __half g_Wc_h[DIM*DIM];

// ---------------- helpers ----------------------------------------------------
__device__ __forceinline__ uint32_t smem_u32(const void* p) {
    return (uint32_t)__cvta_generic_to_shared(p);
}
__device__ __forceinline__ void ldmatrix_x4(uint32_t& r0, uint32_t& r1,
                                            uint32_t& r2, uint32_t& r3, uint32_t addr) {
    asm volatile("ldmatrix.sync.aligned.m8n8.x4.shared.b16 {%0,%1,%2,%3}, [%4];\n"
                 : "=r"(r0), "=r"(r1), "=r"(r2), "=r"(r3) : "r"(addr));
}
__device__ __forceinline__ void ldmatrix_x2(uint32_t& r0, uint32_t& r1, uint32_t addr) {
    asm volatile("ldmatrix.sync.aligned.m8n8.x2.shared.b16 {%0,%1}, [%2];\n"
                 : "=r"(r0), "=r"(r1) : "r"(addr));
}
__device__ __forceinline__ void mma_f16(float c[4],
                                        uint32_t a0, uint32_t a1, uint32_t a2, uint32_t a3,
                                        uint32_t b0, uint32_t b1) {
    asm volatile("mma.sync.aligned.m16n8k16.row.col.f32.f16.f16.f32 "
                 "{%0,%1,%2,%3}, {%4,%5,%6,%7}, {%8,%9}, {%0,%1,%2,%3};\n"
                 : "+f"(c[0]), "+f"(c[1]), "+f"(c[2]), "+f"(c[3])
                 : "r"(a0), "r"(a1), "r"(a2), "r"(a3), "r"(b0), "r"(b1));
}
__device__ __forceinline__ void cp16(uint32_t dst, const void* src) {
    asm volatile("cp.async.cg.shared.global [%0], [%1], 16;\n" :: "r"(dst), "l"(src));
}

// job decode: [0,1536) K tiles, [1536,2048) Q tiles, [2048,3584) V tiles
__device__ __forceinline__ void decode_job(int j, int& type, int& mt, int& ncol0) {
    if (j < 1536)      { type = 0; mt = j >> 1;            ncol0 = (j & 1) * 128; }
    else if (j < 2048) { int r = j - 1536; type = 1; mt = r >> 1; ncol0 = (r & 1) * 128; }
    else               { int r = j - 2048; type = 2; mt = r >> 1; ncol0 = (r & 1) * 128; }
}

// ---------------- prologue kernels -------------------------------------------
__global__ void convert_w3_kernel(const float* __restrict__ s0, __half* __restrict__ h0, __half* __restrict__ l0,
                                  const float* __restrict__ s1, __half* __restrict__ h1, __half* __restrict__ l1,
                                  const float* __restrict__ s2, __half* __restrict__ h2, __half* __restrict__ l2) {
    const float* s; __half *hh, *ll;
    if (blockIdx.y == 0)      { s = s0; hh = h0; ll = l0; }
    else if (blockIdx.y == 1) { s = s1; hh = h1; ll = l1; }
    else                      { s = s2; hh = h2; ll = l2; }
    int i = blockIdx.x * 256 + threadIdx.x;
    float x = s[i];
    __half v = __float2half_rn(x);
    hh[i] = v;
    ll[i] = __float2half_rn(x - __half2float(v));
}

__global__ void convert_h_kernel(const float* __restrict__ src,
                                 __half* __restrict__ hi,
                                 __half* __restrict__ lo) {
    size_t i = ((size_t)blockIdx.x * 256 + threadIdx.x) * 8;
    float4 a = *(const float4*)(src + i);
    float4 b = *(const float4*)(src + i + 4);
    float x[8] = {a.x, a.y, a.z, a.w, b.x, b.y, b.z, b.w};
    uint32_t hw[4], lw[4];
    #pragma unroll
    for (int g = 0; g < 4; ++g) {
        __half h0 = __float2half_rn(x[2*g]);
        __half h1 = __float2half_rn(x[2*g+1]);
        __half l0 = __float2half_rn(x[2*g]   - __half2float(h0));
        __half l1 = __float2half_rn(x[2*g+1] - __half2float(h1));
        hw[g] = (uint32_t)__half_as_ushort(h0) | ((uint32_t)__half_as_ushort(h1) << 16);
        lw[g] = (uint32_t)__half_as_ushort(l0) | ((uint32_t)__half_as_ushort(l1) << 16);
    }
    *(uint4*)(hi + i) = make_uint4(hw[0], hw[1], hw[2], hw[3]);
    *(uint4*)(lo + i) = make_uint4(lw[0], lw[1], lw[2], lw[3]);
}

// ---- fold, stage 1: partial Wc over k-slices.  grid (32, 8), block 256 ------
__global__ void fold_part_kernel(const float* __restrict__ Wf,
                                 const float* __restrict__ Wo1,
                                 float* __restrict__ part) {
    __shared__ float sWf[8][32];
    const int t = threadIdx.x, o0 = blockIdx.x * 8, kz = blockIdx.y * 32;
    {
        int r = t >> 5, hh = t & 31;
        sWf[r][hh] = Wf[(o0 + r) * 256 + kz + hh];
    }
    __syncthreads();
    float acc[8] = {0,0,0,0,0,0,0,0};
    #pragma unroll
    for (int hh = 0; hh < 32; ++hh) {
        float x = Wo1[(kz + hh) * 256 + t];
        #pragma unroll
        for (int r = 0; r < 8; ++r) acc[r] = fmaf(sWf[r][hh], x, acc[r]);
    }
    #pragma unroll
    for (int r = 0; r < 8; ++r)
        part[((size_t)blockIdx.y << 16) + (o0 + r) * 256 + t] = acc[r];
}

// ---- fold, stage 2: reduce partials, fp16 hi, compute bc --------------------
__global__ void fold_reduce_kernel(const float* __restrict__ part,
                                   const float* __restrict__ Wf,
                                   const float* __restrict__ bo1,
                                   const float* __restrict__ bfb,
                                   __half* __restrict__ Wch,
                                   float* __restrict__ bc) {
    const int o = blockIdx.x, t = threadIdx.x;
    float v = 0.f;
    #pragma unroll
    for (int kz = 0; kz < 8; ++kz) v += part[((size_t)kz << 16) + o * 256 + t];
    Wch[o * 256 + t] = __float2half_rn(v);

    __shared__ float red[256];
    red[t] = Wf[o * 256 + t] * bo1[t];
    __syncthreads();
    #pragma unroll
    for (int s = 128; s > 0; s >>= 1) {
        if (t < s) red[t] += red[t + s];
        __syncthreads();
    }
    if (t == 0) bc[o] = red[0] + bfb[o];
}

// ---------------- fused K+Q+V GEMM (persistent, flat job list) ---------------
// 3584 jobs on 296 CTAs. 2-stage pipeline, stage = {Ah,Al,Bh,Bl} x 10240B.
// K jobs: fp16x3 f32-accum -> k1 f32.  Q jobs: same + gathered A -> q1 f32.
// V jobs: 1-pass (hi only; lo loads skipped) -> Wh1 f16.  All with relu+bias.
#define STG3 40960u
#define SMEMF (2 * 40960 + 3072 + 128)

__global__ void __launch_bounds__(256, 2)
gemm_all(const __half* __restrict__ Ah, const __half* __restrict__ Al,
         const __half* __restrict__ Wkh, const __half* __restrict__ Wkl,
         const __half* __restrict__ Wqh, const __half* __restrict__ Wql,
         const __half* __restrict__ Wvh,
         const float* __restrict__ bk, const float* __restrict__ bq,
         const float* __restrict__ bv,
         float* __restrict__ k1, float* __restrict__ q1,
         __half* __restrict__ wh1) {
    extern __shared__ char smem[];
    const uint32_t sb = smem_u32(smem);
    float* sbias = (float*)(smem + 2 * STG3);     // [3][256]
    const int t = threadIdx.x, lane = t & 31, wid = t >> 5;
    const int tb = blockIdx.x;

    if (t < 256) {
        sbias[t]       = bk[t];
        sbias[256 + t] = bq[t];
        sbias[512 + t] = bv[t];
    }

    int tiles = 0;
    for (int j = tb; j < NJOBS; j += NWORK) ++tiles;
    const int QS = tiles * 8;

    auto cp_stage = [&](int q) {
        const int lt = q >> 3, kt = q & 7;
        const int j = tb + lt * NWORK;
        int type, mt, ncol0;
        decode_job(j, type, mt, ncol0);
        const __half* WH = (type == 0) ? Wkh : (type == 1) ? Wqh : Wvh;
        const __half* WL = (type == 1) ? Wql : Wkl;      // unused for V
        const bool isV = (type == 2);
        const uint32_t db = sb + (uint32_t)(q & 1) * STG3;
        #pragma unroll
        for (int u = 0; u < 8; ++u) {
            const int s = t + (u << 8);
            const int id  = s >> 9;           // 0=Ah 1=Al 2=Bh 3=Bl
            if (isV && (id & 1)) continue;    // V: skip lo arrays
            const int row = (s >> 2) & 127;
            const int seg = s & 3;
            const uint32_t dst = db + (uint32_t)(id * 10240 + row * 80 + seg * 16);
            const __half* src;
            if (id < 2) {
                int g = mt * 128 + row;
                if (type == 1) g = (g >> 2) * 12 + 3 * (g & 3);
                src = (id ? Al : Ah) + (size_t)g * 256 + kt * 32 + seg * 8;
            } else {
                src = ((id == 3) ? WL : WH) + (ncol0 + row) * 256 + kt * 32 + seg * 8;
            }
            cp16(dst, src);
        }
        asm volatile("cp.async.commit_group;\n" ::: "memory");
    };

    const int wm = (wid & 1) * 64;
    const int wn = (wid >> 1) * 32;
    const uint32_t aoff = (uint32_t)((wm + (lane & 15)) * 80 + ((lane >> 4) << 4));
    const uint32_t boff = (uint32_t)((lane & 7) * 80 + (((lane >> 3) & 1) << 4));

    float c[4][4][4];
    #pragma unroll
    for (int i = 0; i < 4; ++i)
        #pragma unroll
        for (int j2 = 0; j2 < 4; ++j2)
            #pragma unroll
            for (int e = 0; e < 4; ++e) c[i][j2][e] = 0.f;

    if (QS > 0) cp_stage(0);

    for (int q = 0; q < QS; ++q) {
        const int kt = q & 7;
        const int j = tb + (q >> 3) * NWORK;
        int type, mt, ncol0;
        decode_job(j, type, mt, ncol0);
        const bool isV = (type == 2);

        asm volatile("cp.async.wait_group 0;\n" ::: "memory");
        __syncthreads();
        if (q + 1 < QS) cp_stage(q + 1);

        {
            const uint32_t ab     = sb + (uint32_t)(q & 1) * STG3;
            const uint32_t albase = ab + 10240;
            const uint32_t bhbase = ab + 20480;
            const uint32_t blbase = ab + 30720;
            #pragma unroll
            for (int ks = 0; ks < 32; ks += 16) {
                uint32_t rbh[4][2], rah[4][4];
                #pragma unroll
                for (int j2 = 0; j2 < 4; ++j2) {
                    const uint32_t o = boff + (uint32_t)((wn + 8 * j2) * 80 + ks * 2);
                    ldmatrix_x2(rbh[j2][0], rbh[j2][1], bhbase + o);
                }
                #pragma unroll
                for (int i = 0; i < 4; ++i) {
                    const uint32_t o = aoff + (uint32_t)(i * 16 * 80 + ks * 2);
                    ldmatrix_x4(rah[i][0], rah[i][1], rah[i][2], rah[i][3], ab + o);
                }
                // pass 1: hi*hi (always)
                #pragma unroll
                for (int i = 0; i < 4; ++i)
                    #pragma unroll
                    for (int j2 = 0; j2 < 4; ++j2)
                        mma_f16(c[i][j2], rah[i][0], rah[i][1], rah[i][2], rah[i][3],
                                rbh[j2][0], rbh[j2][1]);
                if (!isV) {
                    uint32_t rbl[4][2], ral[4][4];
                    #pragma unroll
                    for (int j2 = 0; j2 < 4; ++j2) {
                        const uint32_t o = boff + (uint32_t)((wn + 8 * j2) * 80 + ks * 2);
                        ldmatrix_x2(rbl[j2][0], rbl[j2][1], blbase + o);
                    }
                    #pragma unroll
                    for (int i = 0; i < 4; ++i) {
                        const uint32_t o = aoff + (uint32_t)(i * 16 * 80 + ks * 2);
                        ldmatrix_x4(ral[i][0], ral[i][1], ral[i][2], ral[i][3], albase + o);
                    }
                    // pass 2: hi*lo
                    #pragma unroll
                    for (int i = 0; i < 4; ++i)
                        #pragma unroll
                        for (int j2 = 0; j2 < 4; ++j2)
                            mma_f16(c[i][j2], rah[i][0], rah[i][1], rah[i][2], rah[i][3],
                                    rbl[j2][0], rbl[j2][1]);
                    // pass 3: lo*hi
                    #pragma unroll
                    for (int i = 0; i < 4; ++i)
                        #pragma unroll
                        for (int j2 = 0; j2 < 4; ++j2)
                            mma_f16(c[i][j2], ral[i][0], ral[i][1], ral[i][2], ral[i][3],
                                    rbh[j2][0], rbh[j2][1]);
                }
            }
        }

        if (kt == 7) {
            const int gr = lane >> 2, gc = (lane & 3) * 2;
            const int mbase = mt * 128 + wm;
            const float* bb = sbias + type * 256 + ncol0;
            #pragma unroll
            for (int i = 0; i < 4; ++i) {
                #pragma unroll
                for (int j2 = 0; j2 < 4; ++j2) {
                    const int col = wn + 8 * j2 + gc;
                    const float b0v = bb[col], b1v = bb[col + 1];
                    float v0 = fmaxf(c[i][j2][0] + b0v, 0.f);
                    float v1 = fmaxf(c[i][j2][1] + b1v, 0.f);
                    float v2 = fmaxf(c[i][j2][2] + b0v, 0.f);
                    float v3 = fmaxf(c[i][j2][3] + b1v, 0.f);
                    const int r0 = mbase + 16 * i + gr;
                    if (type == 2) {
                        *(__half2*)&wh1[(size_t)r0 * 256 + ncol0 + col] =
                            __floats2half2_rn(v0, v1);
                        *(__half2*)&wh1[(size_t)(r0 + 8) * 256 + ncol0 + col] =
                            __floats2half2_rn(v2, v3);
                    } else {
                        float* C = (type == 0) ? k1 : q1;
                        *(float2*)&C[(size_t)r0 * 256 + ncol0 + col]       = make_float2(v0, v1);
                        *(float2*)&C[(size_t)(r0 + 8) * 256 + ncol0 + col] = make_float2(v2, v3);
                    }
                    c[i][j2][0] = 0.f; c[i][j2][1] = 0.f;
                    c[i][j2][2] = 0.f; c[i][j2][3] = 0.f;
                }
            }
        }
    }
}

// ---------------- out GEMM (fp16x1, R11 config) ------------------------------
__global__ void __launch_bounds__(256, 2)
gemm_out(const __half* __restrict__ Ah, const __half* __restrict__ Wh,
         const float* __restrict__ bias, float* __restrict__ C, int Mtiles) {
    constexpr int STAGES = 4;
    constexpr uint32_t STG = 2 * 10240;
    extern __shared__ char smem[];
    const uint32_t sb = smem_u32(smem);
    float* sbias = (float*)(smem + STAGES * STG);
    const int t = threadIdx.x, lane = t & 31, wid = t >> 5;

    const int y = blockIdx.x & 1;
    const int tb = blockIdx.x >> 1;
    const int NTB = gridDim.x >> 1;
    const int ncol0 = y * 128;

    if (t < 128) sbias[t] = bias[ncol0 + t];

    int tiles = 0;
    for (int mt = tb; mt < Mtiles; mt += NTB) ++tiles;
    const int QS = tiles * 8;

    auto cp_stage = [&](int q) {
        const int lt = q >> 3, kt = q & 7;
        const int mt = tb + lt * NTB;
        const uint32_t db = sb + (uint32_t)(q & 3) * STG;
        #pragma unroll
        for (int u = 0; u < 4; ++u) {
            const int s = t + (u << 8);
            const int id  = s >> 9;
            const int row = (s >> 2) & 127;
            const int seg = s & 3;
            const uint32_t dst = db + (uint32_t)(id * 10240 + row * 80 + seg * 16);
            const __half* src;
            if (id == 0) src = Ah + (size_t)(mt * 128 + row) * 256 + kt * 32 + seg * 8;
            else         src = Wh + (ncol0 + row) * 256 + kt * 32 + seg * 8;
            cp16(dst, src);
        }
        asm volatile("cp.async.commit_group;\n" ::: "memory");
    };

    const int wm = (wid & 1) * 64;
    const int wn = (wid >> 1) * 32;
    const uint32_t aoff = (uint32_t)((wm + (lane & 15)) * 80 + ((lane >> 4) << 4));
    const uint32_t boff = (uint32_t)((lane & 7) * 80 + (((lane >> 3) & 1) << 4));

    float c[4][4][4];
    #pragma unroll
    for (int i = 0; i < 4; ++i)
        #pragma unroll
        for (int j = 0; j < 4; ++j)
            #pragma unroll
            for (int e = 0; e < 4; ++e) c[i][j][e] = 0.f;

    const int npre = QS < 3 ? QS : 3;
    for (int q = 0; q < npre; ++q) cp_stage(q);

    for (int q = 0; q < QS; ++q) {
        const int kt = q & 7;
        asm volatile("cp.async.wait_group 2;\n" ::: "memory");
        __syncthreads();
        if (q + 3 < QS) cp_stage(q + 3);
        {
            const uint32_t ab = sb + (uint32_t)(q & 3) * STG;
            const uint32_t bhbase = ab + 10240;
            #pragma unroll
            for (int ks = 0; ks < 32; ks += 16) {
                uint32_t rbh[4][2], rah[4][4];
                #pragma unroll
                for (int j = 0; j < 4; ++j) {
                    const uint32_t o = boff + (uint32_t)((wn + 8 * j) * 80 + ks * 2);
                    ldmatrix_x2(rbh[j][0], rbh[j][1], bhbase + o);
                }
                #pragma unroll
                for (int i = 0; i < 4; ++i) {
                    const uint32_t o = aoff + (uint32_t)(i * 16 * 80 + ks * 2);
                    ldmatrix_x4(rah[i][0], rah[i][1], rah[i][2], rah[i][3], ab + o);
                }
                #pragma unroll
                for (int i = 0; i < 4; ++i)
                    #pragma unroll
                    for (int j = 0; j < 4; ++j)
                        mma_f16(c[i][j], rah[i][0], rah[i][1], rah[i][2], rah[i][3],
                                rbh[j][0], rbh[j][1]);
            }
        }
        if (kt == 7) {
            const int mt = tb + (q >> 3) * NTB;
            const int gr = lane >> 2, gc = (lane & 3) * 2;
            const int mbase = mt * 128 + wm;
            #pragma unroll
            for (int i = 0; i < 4; ++i) {
                #pragma unroll
                for (int j = 0; j < 4; ++j) {
                    const int col = wn + 8 * j + gc;
                    const float b0v = sbias[col], b1v = sbias[col + 1];
                    float v0 = c[i][j][0] + b0v, v1 = c[i][j][1] + b1v;
                    float v2 = c[i][j][2] + b0v, v3 = c[i][j][3] + b1v;
                    const int r0 = mbase + 16 * i + gr;
                    *(float2*)&C[(size_t)r0 * 256 + ncol0 + col]       = make_float2(v0, v1);
                    *(float2*)&C[(size_t)(r0 + 8) * 256 + ncol0 + col] = make_float2(v2, v3);
                    c[i][j][0] = 0.f; c[i][j][1] = 0.f;
                    c[i][j][2] = 0.f; c[i][j][3] = 0.f;
                }
            }
        }
    }
}

// ---------------- attention ---------------------------------------------------
__global__ void __launch_bounds__(128)
attn_kernel(const float* __restrict__ q1, const float* __restrict__ k1,
            const __half* __restrict__ wh1, const float* __restrict__ label,
            const float* __restrict__ adj, __half* __restrict__ f1h) {
    __shared__ float  sk [NNODE * 256];
    __shared__ __half swh[NNODE * 256];
    __shared__ float  sq [4 * 256];
    __shared__ float  sadj[4 * NNODE];
    __shared__ float  slab[NNODE];

    const int b = blockIdx.x, t = threadIdx.x;

    const float4* k4 = (const float4*)(k1  + (size_t)b * NNODE * 256);
    const uint4*  w4 = (const uint4*)(wh1 + (size_t)b * NNODE * 256);
    const float4* q4 = (const float4*)(q1  + (size_t)b * 4 * 256);
    float4* dk = (float4*)sk;
    uint4*  dw = (uint4*)swh;
    float4* dq = (float4*)sq;
    #pragma unroll
    for (int u = 0; u < 6; ++u) dk[t + 128 * u] = k4[t + 128 * u];
    #pragma unroll
    for (int u = 0; u < 3; ++u) dw[t + 128 * u] = w4[t + 128 * u];
    #pragma unroll
    for (int u = 0; u < 2; ++u) dq[t + 128 * u] = q4[t + 128 * u];
    if (t < NNODE) slab[t] = label[b * NNODE + t];
    if (t < 4 * NNODE) {
        int i = t / NNODE, m = t % NNODE;
        sadj[t] = adj[(3 * i) * NNODE + m];
    }
    __syncthreads();

    const int w = t >> 5, l = t & 31;
    float qv[8];
    {
        const float4* qp = (const float4*)(sq + w * 256 + l * 8);
        float4 a = qp[0], bq_ = qp[1];
        qv[0]=a.x; qv[1]=a.y; qv[2]=a.z; qv[3]=a.w;
        qv[4]=bq_.x; qv[5]=bq_.y; qv[6]=bq_.z; qv[7]=bq_.w;
    }
    float s[NNODE];
    #pragma unroll
    for (int m = 0; m < NNODE; ++m) {
        const float4* kp = (const float4*)(sk + m * 256 + l * 8);
        float4 a = kp[0], bb = kp[1];
        s[m] = qv[0]*a.x + qv[1]*a.y + qv[2]*a.z + qv[3]*a.w
             + qv[4]*bb.x + qv[5]*bb.y + qv[6]*bb.z + qv[7]*bb.w;
    }
    #pragma unroll
    for (int m = 0; m < NNODE; ++m)
        #pragma unroll
        for (int off = 16; off > 0; off >>= 1)
            s[m] += __shfl_xor_sync(0xffffffffu, s[m], off);

    float mx = -3.0e38f;
    #pragma unroll
    for (int m = 0; m < NNODE; ++m) {
        float sm = (sadj[w * NNODE + m] > 0.5f) ? s[m] : -9.0e15f;
        s[m] = sm;
        mx = fmaxf(mx, sm);
    }
    float sum = 0.f;
    #pragma unroll
    for (int m = 0; m < NNODE; ++m) { float p = expf(s[m] - mx); s[m] = p; sum += p; }
    const float inv = 1.f / sum;
    #pragma unroll
    for (int m = 0; m < NNODE; ++m) s[m] = s[m] * inv * slab[m];

    float o[8] = {0,0,0,0,0,0,0,0};
    #pragma unroll
    for (int m = 0; m < NNODE; ++m) {
        const __half2* wp = (const __half2*)(swh + m * 256 + l * 8);
        float2 a0 = __half22float2(wp[0]);
        float2 a1 = __half22float2(wp[1]);
        float2 a2 = __half22float2(wp[2]);
        float2 a3 = __half22float2(wp[3]);
        float am = s[m];
        o[0] = fmaf(am, a0.x, o[0]); o[1] = fmaf(am, a0.y, o[1]);
        o[2] = fmaf(am, a1.x, o[2]); o[3] = fmaf(am, a1.y, o[3]);
        o[4] = fmaf(am, a2.x, o[4]); o[5] = fmaf(am, a2.y, o[5]);
        o[6] = fmaf(am, a3.x, o[6]); o[7] = fmaf(am, a3.y, o[7]);
    }
    uint32_t pk[4];
    #pragma unroll
    for (int g = 0; g < 4; ++g) {
        __half2 h2 = __floats2half2_rn(o[2*g], o[2*g+1]);
        pk[g] = *(uint32_t*)&h2;
    }
    const size_t idx = (size_t)(b * 4 + w) * 256 + l * 8;
    *(uint4*)(f1h + idx) = make_uint4(pk[0], pk[1], pk[2], pk[3]);
}

// ---------------- host launch -------------------------------------------------
extern "C" void kernel_launch(void* const* d_in, const int* in_sizes, int n_in,
                              void* d_out, int out_size) {
    const float* h     = (const float*)d_in[0];
    const float* adj   = (const float*)d_in[1];
    const float* label = (const float*)d_in[2];
    const float* Wv    = (const float*)d_in[3];
    const float* bv    = (const float*)d_in[4];
    const float* Wk    = (const float*)d_in[5];
    const float* bk    = (const float*)d_in[6];
    const float* Wq    = (const float*)d_in[7];
    const float* bq    = (const float*)d_in[8];
    const float* Wo1   = (const float*)d_in[9];
    const float* bo1   = (const float*)d_in[10];
    const float* Wf    = (const float*)d_in[11];
    const float* bf    = (const float*)d_in[12];
    float* out = (float*)d_out;

    float *p_k1, *p_q1, *p_bc, *p_part;
    __half *p_hh, *p_hl, *p_f1h, *p_Wh1;
    __half *p_Wvh, *p_Wvl, *p_Wkh, *p_Wkl, *p_Wqh, *p_Wql, *p_Wch;
    cudaGetSymbolAddress((void**)&p_Wh1, g_Wh1);
    cudaGetSymbolAddress((void**)&p_k1,  g_k1);
    cudaGetSymbolAddress((void**)&p_q1,  g_q1);
    cudaGetSymbolAddress((void**)&p_bc,  g_bc);
    cudaGetSymbolAddress((void**)&p_part, g_Wc_part);
    cudaGetSymbolAddress((void**)&p_hh,  g_hh);
    cudaGetSymbolAddress((void**)&p_hl,  g_hl);
    cudaGetSymbolAddress((void**)&p_f1h, g_f1h);
    cudaGetSymbolAddress((void**)&p_Wvh, g_Wv_h);
    cudaGetSymbolAddress((void**)&p_Wvl, g_Wv_l);
    cudaGetSymbolAddress((void**)&p_Wkh, g_Wk_h);
    cudaGetSymbolAddress((void**)&p_Wkl, g_Wk_l);
    cudaGetSymbolAddress((void**)&p_Wqh, g_Wq_h);
    cudaGetSymbolAddress((void**)&p_Wql, g_Wq_l);
    cudaGetSymbolAddress((void**)&p_Wch, g_Wc_h);

    const int SMEM1 = 4 * 20480 + 1024;
    cudaFuncSetAttribute(gemm_all,
                         cudaFuncAttributeMaxDynamicSharedMemorySize, SMEMF);
    cudaFuncSetAttribute(gemm_out,
                         cudaFuncAttributeMaxDynamicSharedMemorySize, SMEM1);

    convert_h_kernel<<<12288, 256>>>(h, p_hh, p_hl);                       // 1
    convert_w3_kernel<<<dim3(256, 3), 256>>>(Wv, p_Wvh, p_Wvl,
                                             Wk, p_Wkh, p_Wkl,
                                             Wq, p_Wqh, p_Wql);            // 2
    fold_part_kernel<<<dim3(32, 8), 256>>>(Wf, Wo1, p_part);               // 3
    // fused K+Q+V GEMM (3584 jobs / 296 persistent CTAs)                  // 4
    gemm_all<<<NWORK, 256, SMEMF>>>(
        p_hh, p_hl, p_Wkh, p_Wkl, p_Wqh, p_Wql, p_Wvh,
        bk, bq, bv, p_k1, p_q1, p_Wh1);
    fold_reduce_kernel<<<256, 256>>>(p_part, Wf, bo1, bf, p_Wch, p_bc);    // 5
    attn_kernel<<<BATCH, 128>>>(p_q1, p_k1, p_Wh1, label, adj, p_f1h);     // 6
    // out GEMM (fp16x1) straight into d_out                               // 7
    gemm_out<<<296, 256, SMEM1>>>(p_f1h, p_Wch, p_bc, out, M_SEL / 128);
}

// round 17
// speedup vs baseline: 1.0892x; 1.0234x over previous
#include <cuda_runtime.h>
#include <cuda_fp16.h>
#include <cstdint>
#include <cstddef>

// ============================================================================
// GAT fusion, B=8192, N=12, D=256, SEL={0,3,6,9}.  sm_100 legacy-mma edition.
// Measured: f32-accum HMMA floor ~17cyc/SMSP -> gemm_all (242us) is at HW
// floor. This round: attention kernel occupancy/overlap (cp.async staging,
// q direct-to-reg, smem 22.3->18.7KB) + launch reorder (no serial gaps in
// gemm_all -> attn -> gemm_out chain; convert_h lands at ncu slot 4).
// K,Q fp16x3 (softmax-accurate); V,out fp16x1; Wh1/f1 fp16 intermediates.
// ============================================================================

#define BATCH   8192
#define NNODE   12
#define DIM     256
#define M_VK    (BATCH * NNODE)     // 98304
#define M_SEL   (BATCH * 4)         // 32768
#define NWORK   296                 // persistent workers (2 CTA/SM * 148)
#define NJOBS   3584                // K 1536 + Q 512 + V 1536

// ---------------- scratch (device globals; no allocation) -------------------
__device__ __half g_hh[M_VK * DIM], g_hl[M_VK * DIM];    // h split (fp16)
__device__ __half g_Wh1[M_VK * DIM];                      // V output, fp16
__device__ float g_k1 [M_VK * DIM];
__device__ float g_q1 [M_SEL * DIM];
__device__ __half g_f1h[M_SEL * DIM];
__device__ float g_bc [DIM];
__device__ float g_Wc_part[8 * DIM * DIM];
__device__ __half g_Wv_h[DIM*DIM], g_Wv_l[DIM*DIM];
__device__ __half g_Wk_h[DIM*DIM], g_Wk_l[DIM*DIM];
__device__ __half g_Wq_h[DIM*DIM], g_Wq_l[DIM*DIM];
__device__ __half g_Wc_h[DIM*DIM];

// ---------------- helpers ----------------------------------------------------
__device__ __forceinline__ uint32_t smem_u32(const void* p) {
    return (uint32_t)__cvta_generic_to_shared(p);
}
__device__ __forceinline__ void ldmatrix_x4(uint32_t& r0, uint32_t& r1,
                                            uint32_t& r2, uint32_t& r3, uint32_t addr) {
    asm volatile("ldmatrix.sync.aligned.m8n8.x4.shared.b16 {%0,%1,%2,%3}, [%4];\n"
                 : "=r"(r0), "=r"(r1), "=r"(r2), "=r"(r3) : "r"(addr));
}
__device__ __forceinline__ void ldmatrix_x2(uint32_t& r0, uint32_t& r1, uint32_t addr) {
    asm volatile("ldmatrix.sync.aligned.m8n8.x2.shared.b16 {%0,%1}, [%2];\n"
                 : "=r"(r0), "=r"(r1) : "r"(addr));
}
__device__ __forceinline__ void mma_f16(float c[4],
                                        uint32_t a0, uint32_t a1, uint32_t a2, uint32_t a3,
                                        uint32_t b0, uint32_t b1) {
    asm volatile("mma.sync.aligned.m16n8k16.row.col.f32.f16.f16.f32 "
                 "{%0,%1,%2,%3}, {%4,%5,%6,%7}, {%8,%9}, {%0,%1,%2,%3};\n"
                 : "+f"(c[0]), "+f"(c[1]), "+f"(c[2]), "+f"(c[3])
                 : "r"(a0), "r"(a1), "r"(a2), "r"(a3), "r"(b0), "r"(b1));
}
__device__ __forceinline__ void cp16(uint32_t dst, const void* src) {
    asm volatile("cp.async.cg.shared.global [%0], [%1], 16;\n" :: "r"(dst), "l"(src));
}

// job decode: [0,1536) K tiles, [1536,2048) Q tiles, [2048,3584) V tiles
__device__ __forceinline__ void decode_job(int j, int& type, int& mt, int& ncol0) {
    if (j < 1536)      { type = 0; mt = j >> 1;            ncol0 = (j & 1) * 128; }
    else if (j < 2048) { int r = j - 1536; type = 1; mt = r >> 1; ncol0 = (r & 1) * 128; }
    else               { int r = j - 2048; type = 2; mt = r >> 1; ncol0 = (r & 1) * 128; }
}

// ---------------- prologue kernels -------------------------------------------
__global__ void convert_w3_kernel(const float* __restrict__ s0, __half* __restrict__ h0, __half* __restrict__ l0,
                                  const float* __restrict__ s1, __half* __restrict__ h1, __half* __restrict__ l1,
                                  const float* __restrict__ s2, __half* __restrict__ h2, __half* __restrict__ l2) {
    const float* s; __half *hh, *ll;
    if (blockIdx.y == 0)      { s = s0; hh = h0; ll = l0; }
    else if (blockIdx.y == 1) { s = s1; hh = h1; ll = l1; }
    else                      { s = s2; hh = h2; ll = l2; }
    int i = blockIdx.x * 256 + threadIdx.x;
    float x = s[i];
    __half v = __float2half_rn(x);
    hh[i] = v;
    ll[i] = __float2half_rn(x - __half2float(v));
}

__global__ void convert_h_kernel(const float* __restrict__ src,
                                 __half* __restrict__ hi,
                                 __half* __restrict__ lo) {
    size_t i = ((size_t)blockIdx.x * 256 + threadIdx.x) * 8;
    float4 a = *(const float4*)(src + i);
    float4 b = *(const float4*)(src + i + 4);
    float x[8] = {a.x, a.y, a.z, a.w, b.x, b.y, b.z, b.w};
    uint32_t hw[4], lw[4];
    #pragma unroll
    for (int g = 0; g < 4; ++g) {
        __half h0 = __float2half_rn(x[2*g]);
        __half h1 = __float2half_rn(x[2*g+1]);
        __half l0 = __float2half_rn(x[2*g]   - __half2float(h0));
        __half l1 = __float2half_rn(x[2*g+1] - __half2float(h1));
        hw[g] = (uint32_t)__half_as_ushort(h0) | ((uint32_t)__half_as_ushort(h1) << 16);
        lw[g] = (uint32_t)__half_as_ushort(l0) | ((uint32_t)__half_as_ushort(l1) << 16);
    }
    *(uint4*)(hi + i) = make_uint4(hw[0], hw[1], hw[2], hw[3]);
    *(uint4*)(lo + i) = make_uint4(lw[0], lw[1], lw[2], lw[3]);
}

// ---- fold, stage 1: partial Wc over k-slices.  grid (32, 8), block 256 ------
__global__ void fold_part_kernel(const float* __restrict__ Wf,
                                 const float* __restrict__ Wo1,
                                 float* __restrict__ part) {
    __shared__ float sWf[8][32];
    const int t = threadIdx.x, o0 = blockIdx.x * 8, kz = blockIdx.y * 32;
    {
        int r = t >> 5, hh = t & 31;
        sWf[r][hh] = Wf[(o0 + r) * 256 + kz + hh];
    }
    __syncthreads();
    float acc[8] = {0,0,0,0,0,0,0,0};
    #pragma unroll
    for (int hh = 0; hh < 32; ++hh) {
        float x = Wo1[(kz + hh) * 256 + t];
        #pragma unroll
        for (int r = 0; r < 8; ++r) acc[r] = fmaf(sWf[r][hh], x, acc[r]);
    }
    #pragma unroll
    for (int r = 0; r < 8; ++r)
        part[((size_t)blockIdx.y << 16) + (o0 + r) * 256 + t] = acc[r];
}

// ---- fold, stage 2: reduce partials, fp16 hi, compute bc --------------------
__global__ void fold_reduce_kernel(const float* __restrict__ part,
                                   const float* __restrict__ Wf,
                                   const float* __restrict__ bo1,
                                   const float* __restrict__ bfb,
                                   __half* __restrict__ Wch,
                                   float* __restrict__ bc) {
    const int o = blockIdx.x, t = threadIdx.x;
    float v = 0.f;
    #pragma unroll
    for (int kz = 0; kz < 8; ++kz) v += part[((size_t)kz << 16) + o * 256 + t];
    Wch[o * 256 + t] = __float2half_rn(v);

    __shared__ float red[256];
    red[t] = Wf[o * 256 + t] * bo1[t];
    __syncthreads();
    #pragma unroll
    for (int s = 128; s > 0; s >>= 1) {
        if (t < s) red[t] += red[t + s];
        __syncthreads();
    }
    if (t == 0) bc[o] = red[0] + bfb[o];
}

// ---------------- fused K+Q+V GEMM (persistent, flat job list) ---------------
#define STG3 40960u
#define SMEMF (2 * 40960 + 3072 + 128)

__global__ void __launch_bounds__(256, 2)
gemm_all(const __half* __restrict__ Ah, const __half* __restrict__ Al,
         const __half* __restrict__ Wkh, const __half* __restrict__ Wkl,
         const __half* __restrict__ Wqh, const __half* __restrict__ Wql,
         const __half* __restrict__ Wvh,
         const float* __restrict__ bk, const float* __restrict__ bq,
         const float* __restrict__ bv,
         float* __restrict__ k1, float* __restrict__ q1,
         __half* __restrict__ wh1) {
    extern __shared__ char smem[];
    const uint32_t sb = smem_u32(smem);
    float* sbias = (float*)(smem + 2 * STG3);     // [3][256]
    const int t = threadIdx.x, lane = t & 31, wid = t >> 5;
    const int tb = blockIdx.x;

    if (t < 256) {
        sbias[t]       = bk[t];
        sbias[256 + t] = bq[t];
        sbias[512 + t] = bv[t];
    }

    int tiles = 0;
    for (int j = tb; j < NJOBS; j += NWORK) ++tiles;
    const int QS = tiles * 8;

    auto cp_stage = [&](int q) {
        const int lt = q >> 3, kt = q & 7;
        const int j = tb + lt * NWORK;
        int type, mt, ncol0;
        decode_job(j, type, mt, ncol0);
        const __half* WH = (type == 0) ? Wkh : (type == 1) ? Wqh : Wvh;
        const __half* WL = (type == 1) ? Wql : Wkl;      // unused for V
        const bool isV = (type == 2);
        const uint32_t db = sb + (uint32_t)(q & 1) * STG3;
        #pragma unroll
        for (int u = 0; u < 8; ++u) {
            const int s = t + (u << 8);
            const int id  = s >> 9;           // 0=Ah 1=Al 2=Bh 3=Bl
            if (isV && (id & 1)) continue;    // V: skip lo arrays
            const int row = (s >> 2) & 127;
            const int seg = s & 3;
            const uint32_t dst = db + (uint32_t)(id * 10240 + row * 80 + seg * 16);
            const __half* src;
            if (id < 2) {
                int g = mt * 128 + row;
                if (type == 1) g = (g >> 2) * 12 + 3 * (g & 3);
                src = (id ? Al : Ah) + (size_t)g * 256 + kt * 32 + seg * 8;
            } else {
                src = ((id == 3) ? WL : WH) + (ncol0 + row) * 256 + kt * 32 + seg * 8;
            }
            cp16(dst, src);
        }
        asm volatile("cp.async.commit_group;\n" ::: "memory");
    };

    const int wm = (wid & 1) * 64;
    const int wn = (wid >> 1) * 32;
    const uint32_t aoff = (uint32_t)((wm + (lane & 15)) * 80 + ((lane >> 4) << 4));
    const uint32_t boff = (uint32_t)((lane & 7) * 80 + (((lane >> 3) & 1) << 4));

    float c[4][4][4];
    #pragma unroll
    for (int i = 0; i < 4; ++i)
        #pragma unroll
        for (int j2 = 0; j2 < 4; ++j2)
            #pragma unroll
            for (int e = 0; e < 4; ++e) c[i][j2][e] = 0.f;

    if (QS > 0) cp_stage(0);

    for (int q = 0; q < QS; ++q) {
        const int kt = q & 7;
        const int j = tb + (q >> 3) * NWORK;
        int type, mt, ncol0;
        decode_job(j, type, mt, ncol0);
        const bool isV = (type == 2);

        asm volatile("cp.async.wait_group 0;\n" ::: "memory");
        __syncthreads();
        if (q + 1 < QS) cp_stage(q + 1);

        {
            const uint32_t ab     = sb + (uint32_t)(q & 1) * STG3;
            const uint32_t albase = ab + 10240;
            const uint32_t bhbase = ab + 20480;
            const uint32_t blbase = ab + 30720;
            #pragma unroll
            for (int ks = 0; ks < 32; ks += 16) {
                uint32_t rbh[4][2], rah[4][4];
                #pragma unroll
                for (int j2 = 0; j2 < 4; ++j2) {
                    const uint32_t o = boff + (uint32_t)((wn + 8 * j2) * 80 + ks * 2);
                    ldmatrix_x2(rbh[j2][0], rbh[j2][1], bhbase + o);
                }
                #pragma unroll
                for (int i = 0; i < 4; ++i) {
                    const uint32_t o = aoff + (uint32_t)(i * 16 * 80 + ks * 2);
                    ldmatrix_x4(rah[i][0], rah[i][1], rah[i][2], rah[i][3], ab + o);
                }
                // pass 1: hi*hi (always)
                #pragma unroll
                for (int i = 0; i < 4; ++i)
                    #pragma unroll
                    for (int j2 = 0; j2 < 4; ++j2)
                        mma_f16(c[i][j2], rah[i][0], rah[i][1], rah[i][2], rah[i][3],
                                rbh[j2][0], rbh[j2][1]);
                if (!isV) {
                    uint32_t rbl[4][2], ral[4][4];
                    #pragma unroll
                    for (int j2 = 0; j2 < 4; ++j2) {
                        const uint32_t o = boff + (uint32_t)((wn + 8 * j2) * 80 + ks * 2);
                        ldmatrix_x2(rbl[j2][0], rbl[j2][1], blbase + o);
                    }
                    #pragma unroll
                    for (int i = 0; i < 4; ++i) {
                        const uint32_t o = aoff + (uint32_t)(i * 16 * 80 + ks * 2);
                        ldmatrix_x4(ral[i][0], ral[i][1], ral[i][2], ral[i][3], albase + o);
                    }
                    // pass 2: hi*lo
                    #pragma unroll
                    for (int i = 0; i < 4; ++i)
                        #pragma unroll
                        for (int j2 = 0; j2 < 4; ++j2)
                            mma_f16(c[i][j2], rah[i][0], rah[i][1], rah[i][2], rah[i][3],
                                    rbl[j2][0], rbl[j2][1]);
                    // pass 3: lo*hi
                    #pragma unroll
                    for (int i = 0; i < 4; ++i)
                        #pragma unroll
                        for (int j2 = 0; j2 < 4; ++j2)
                            mma_f16(c[i][j2], ral[i][0], ral[i][1], ral[i][2], ral[i][3],
                                    rbh[j2][0], rbh[j2][1]);
                }
            }
        }

        if (kt == 7) {
            const int gr = lane >> 2, gc = (lane & 3) * 2;
            const int mbase = mt * 128 + wm;
            const float* bb = sbias + type * 256 + ncol0;
            #pragma unroll
            for (int i = 0; i < 4; ++i) {
                #pragma unroll
                for (int j2 = 0; j2 < 4; ++j2) {
                    const int col = wn + 8 * j2 + gc;
                    const float b0v = bb[col], b1v = bb[col + 1];
                    float v0 = fmaxf(c[i][j2][0] + b0v, 0.f);
                    float v1 = fmaxf(c[i][j2][1] + b1v, 0.f);
                    float v2 = fmaxf(c[i][j2][2] + b0v, 0.f);
                    float v3 = fmaxf(c[i][j2][3] + b1v, 0.f);
                    const int r0 = mbase + 16 * i + gr;
                    if (type == 2) {
                        *(__half2*)&wh1[(size_t)r0 * 256 + ncol0 + col] =
                            __floats2half2_rn(v0, v1);
                        *(__half2*)&wh1[(size_t)(r0 + 8) * 256 + ncol0 + col] =
                            __floats2half2_rn(v2, v3);
                    } else {
                        float* C = (type == 0) ? k1 : q1;
                        *(float2*)&C[(size_t)r0 * 256 + ncol0 + col]       = make_float2(v0, v1);
                        *(float2*)&C[(size_t)(r0 + 8) * 256 + ncol0 + col] = make_float2(v2, v3);
                    }
                    c[i][j2][0] = 0.f; c[i][j2][1] = 0.f;
                    c[i][j2][2] = 0.f; c[i][j2][3] = 0.f;
                }
            }
        }
    }
}

// ---------------- out GEMM (fp16x1) ------------------------------------------
__global__ void __launch_bounds__(256, 2)
gemm_out(const __half* __restrict__ Ah, const __half* __restrict__ Wh,
         const float* __restrict__ bias, float* __restrict__ C, int Mtiles) {
    constexpr int STAGES = 4;
    constexpr uint32_t STG = 2 * 10240;
    extern __shared__ char smem[];
    const uint32_t sb = smem_u32(smem);
    float* sbias = (float*)(smem + STAGES * STG);
    const int t = threadIdx.x, lane = t & 31, wid = t >> 5;

    const int y = blockIdx.x & 1;
    const int tb = blockIdx.x >> 1;
    const int NTB = gridDim.x >> 1;
    const int ncol0 = y * 128;

    if (t < 128) sbias[t] = bias[ncol0 + t];

    int tiles = 0;
    for (int mt = tb; mt < Mtiles; mt += NTB) ++tiles;
    const int QS = tiles * 8;

    auto cp_stage = [&](int q) {
        const int lt = q >> 3, kt = q & 7;
        const int mt = tb + lt * NTB;
        const uint32_t db = sb + (uint32_t)(q & 3) * STG;
        #pragma unroll
        for (int u = 0; u < 4; ++u) {
            const int s = t + (u << 8);
            const int id  = s >> 9;
            const int row = (s >> 2) & 127;
            const int seg = s & 3;
            const uint32_t dst = db + (uint32_t)(id * 10240 + row * 80 + seg * 16);
            const __half* src;
            if (id == 0) src = Ah + (size_t)(mt * 128 + row) * 256 + kt * 32 + seg * 8;
            else         src = Wh + (ncol0 + row) * 256 + kt * 32 + seg * 8;
            cp16(dst, src);
        }
        asm volatile("cp.async.commit_group;\n" ::: "memory");
    };

    const int wm = (wid & 1) * 64;
    const int wn = (wid >> 1) * 32;
    const uint32_t aoff = (uint32_t)((wm + (lane & 15)) * 80 + ((lane >> 4) << 4));
    const uint32_t boff = (uint32_t)((lane & 7) * 80 + (((lane >> 3) & 1) << 4));

    float c[4][4][4];
    #pragma unroll
    for (int i = 0; i < 4; ++i)
        #pragma unroll
        for (int j = 0; j < 4; ++j)
            #pragma unroll
            for (int e = 0; e < 4; ++e) c[i][j][e] = 0.f;

    const int npre = QS < 3 ? QS : 3;
    for (int q = 0; q < npre; ++q) cp_stage(q);

    for (int q = 0; q < QS; ++q) {
        const int kt = q & 7;
        asm volatile("cp.async.wait_group 2;\n" ::: "memory");
        __syncthreads();
        if (q + 3 < QS) cp_stage(q + 3);
        {
            const uint32_t ab = sb + (uint32_t)(q & 3) * STG;
            const uint32_t bhbase = ab + 10240;
            #pragma unroll
            for (int ks = 0; ks < 32; ks += 16) {
                uint32_t rbh[4][2], rah[4][4];
                #pragma unroll
                for (int j = 0; j < 4; ++j) {
                    const uint32_t o = boff + (uint32_t)((wn + 8 * j) * 80 + ks * 2);
                    ldmatrix_x2(rbh[j][0], rbh[j][1], bhbase + o);
                }
                #pragma unroll
                for (int i = 0; i < 4; ++i) {
                    const uint32_t o = aoff + (uint32_t)(i * 16 * 80 + ks * 2);
                    ldmatrix_x4(rah[i][0], rah[i][1], rah[i][2], rah[i][3], ab + o);
                }
                #pragma unroll
                for (int i = 0; i < 4; ++i)
                    #pragma unroll
                    for (int j = 0; j < 4; ++j)
                        mma_f16(c[i][j], rah[i][0], rah[i][1], rah[i][2], rah[i][3],
                                rbh[j][0], rbh[j][1]);
            }
        }
        if (kt == 7) {
            const int mt = tb + (q >> 3) * NTB;
            const int gr = lane >> 2, gc = (lane & 3) * 2;
            const int mbase = mt * 128 + wm;
            #pragma unroll
            for (int i = 0; i < 4; ++i) {
                #pragma unroll
                for (int j = 0; j < 4; ++j) {
                    const int col = wn + 8 * j + gc;
                    const float b0v = sbias[col], b1v = sbias[col + 1];
                    float v0 = c[i][j][0] + b0v, v1 = c[i][j][1] + b1v;
                    float v2 = c[i][j][2] + b0v, v3 = c[i][j][3] + b1v;
                    const int r0 = mbase + 16 * i + gr;
                    *(float2*)&C[(size_t)r0 * 256 + ncol0 + col]       = make_float2(v0, v1);
                    *(float2*)&C[(size_t)(r0 + 8) * 256 + ncol0 + col] = make_float2(v2, v3);
                    c[i][j][0] = 0.f; c[i][j][1] = 0.f;
                    c[i][j][2] = 0.f; c[i][j][3] = 0.f;
                }
            }
        }
    }
}

// ---------------- attention ---------------------------------------------------
// block = 128 thr = one batch; warp w -> sel row (node 3w).
// cp.async staging for k1 (f32) + Wh1 (f16); q loaded straight to registers.
// smem 18.7KB -> 5 blocks/SM.
__global__ void __launch_bounds__(128)
attn_kernel(const float* __restrict__ q1, const float* __restrict__ k1,
            const __half* __restrict__ wh1, const float* __restrict__ label,
            const float* __restrict__ adj, __half* __restrict__ f1h) {
    __shared__ float  sk [NNODE * 256];     // 12 KB
    __shared__ __half swh[NNODE * 256];     // 6 KB
    __shared__ float  sadj[4 * NNODE];
    __shared__ float  slab[NNODE];

    const int b = blockIdx.x, t = threadIdx.x;
    const int w = t >> 5, l = t & 31;

    // async staging of k1 (768 x 16B) and wh1 (384 x 16B)
    const uint32_t skb = smem_u32(sk), swb = smem_u32(swh);
    const char* ksrc = (const char*)(k1  + (size_t)b * NNODE * 256);
    const char* wsrc = (const char*)(wh1 + (size_t)b * NNODE * 256);
    #pragma unroll
    for (int u = 0; u < 6; ++u)
        cp16(skb + (uint32_t)(t + 128 * u) * 16, ksrc + (size_t)(t + 128 * u) * 16);
    #pragma unroll
    for (int u = 0; u < 3; ++u)
        cp16(swb + (uint32_t)(t + 128 * u) * 16, wsrc + (size_t)(t + 128 * u) * 16);

    // q direct to registers (issues under the async copies)
    const float4* qp = (const float4*)(q1 + (size_t)b * 4 * 256 + w * 256 + l * 8);
    float4 qa = qp[0], qb = qp[1];

    if (t < NNODE) slab[t] = label[b * NNODE + t];
    if (t < 4 * NNODE) {
        int i = t / NNODE, m = t % NNODE;
        sadj[t] = adj[(3 * i) * NNODE + m];
    }

    asm volatile("cp.async.commit_group;\n" ::: "memory");
    asm volatile("cp.async.wait_group 0;\n" ::: "memory");
    __syncthreads();

    float s[NNODE];
    #pragma unroll
    for (int m = 0; m < NNODE; ++m) {
        const float4* kp = (const float4*)(sk + m * 256 + l * 8);
        float4 a = kp[0], bb = kp[1];
        s[m] = qa.x*a.x + qa.y*a.y + qa.z*a.z + qa.w*a.w
             + qb.x*bb.x + qb.y*bb.y + qb.z*bb.z + qb.w*bb.w;
    }
    #pragma unroll
    for (int m = 0; m < NNODE; ++m)
        #pragma unroll
        for (int off = 16; off > 0; off >>= 1)
            s[m] += __shfl_xor_sync(0xffffffffu, s[m], off);

    float mx = -3.0e38f;
    #pragma unroll
    for (int m = 0; m < NNODE; ++m) {
        float sm = (sadj[w * NNODE + m] > 0.5f) ? s[m] : -9.0e15f;
        s[m] = sm;
        mx = fmaxf(mx, sm);
    }
    float sum = 0.f;
    #pragma unroll
    for (int m = 0; m < NNODE; ++m) { float p = expf(s[m] - mx); s[m] = p; sum += p; }
    const float inv = 1.f / sum;
    #pragma unroll
    for (int m = 0; m < NNODE; ++m) s[m] = s[m] * inv * slab[m];

    float o[8] = {0,0,0,0,0,0,0,0};
    #pragma unroll
    for (int m = 0; m < NNODE; ++m) {
        const __half2* wp = (const __half2*)(swh + m * 256 + l * 8);
        float2 a0 = __half22float2(wp[0]);
        float2 a1 = __half22float2(wp[1]);
        float2 a2 = __half22float2(wp[2]);
        float2 a3 = __half22float2(wp[3]);
        float am = s[m];
        o[0] = fmaf(am, a0.x, o[0]); o[1] = fmaf(am, a0.y, o[1]);
        o[2] = fmaf(am, a1.x, o[2]); o[3] = fmaf(am, a1.y, o[3]);
        o[4] = fmaf(am, a2.x, o[4]); o[5] = fmaf(am, a2.y, o[5]);
        o[6] = fmaf(am, a3.x, o[6]); o[7] = fmaf(am, a3.y, o[7]);
    }
    uint32_t pk[4];
    #pragma unroll
    for (int g = 0; g < 4; ++g) {
        __half2 h2 = __floats2half2_rn(o[2*g], o[2*g+1]);
        pk[g] = *(uint32_t*)&h2;
    }
    const size_t idx = (size_t)(b * 4 + w) * 256 + l * 8;
    *(uint4*)(f1h + idx) = make_uint4(pk[0], pk[1], pk[2], pk[3]);
}

// ---------------- host launch -------------------------------------------------
extern "C" void kernel_launch(void* const* d_in, const int* in_sizes, int n_in,
                              void* d_out, int out_size) {
    const float* h     = (const float*)d_in[0];
    const float* adj   = (const float*)d_in[1];
    const float* label = (const float*)d_in[2];
    const float* Wv    = (const float*)d_in[3];
    const float* bv    = (const float*)d_in[4];
    const float* Wk    = (const float*)d_in[5];
    const float* bk    = (const float*)d_in[6];
    const float* Wq    = (const float*)d_in[7];
    const float* bq    = (const float*)d_in[8];
    const float* Wo1   = (const float*)d_in[9];
    const float* bo1   = (const float*)d_in[10];
    const float* Wf    = (const float*)d_in[11];
    const float* bf    = (const float*)d_in[12];
    float* out = (float*)d_out;

    float *p_k1, *p_q1, *p_bc, *p_part;
    __half *p_hh, *p_hl, *p_f1h, *p_Wh1;
    __half *p_Wvh, *p_Wvl, *p_Wkh, *p_Wkl, *p_Wqh, *p_Wql, *p_Wch;
    cudaGetSymbolAddress((void**)&p_Wh1, g_Wh1);
    cudaGetSymbolAddress((void**)&p_k1,  g_k1);
    cudaGetSymbolAddress((void**)&p_q1,  g_q1);
    cudaGetSymbolAddress((void**)&p_bc,  g_bc);
    cudaGetSymbolAddress((void**)&p_part, g_Wc_part);
    cudaGetSymbolAddress((void**)&p_hh,  g_hh);
    cudaGetSymbolAddress((void**)&p_hl,  g_hl);
    cudaGetSymbolAddress((void**)&p_f1h, g_f1h);
    cudaGetSymbolAddress((void**)&p_Wvh, g_Wv_h);
    cudaGetSymbolAddress((void**)&p_Wvl, g_Wv_l);
    cudaGetSymbolAddress((void**)&p_Wkh, g_Wk_h);
    cudaGetSymbolAddress((void**)&p_Wkl, g_Wk_l);
    cudaGetSymbolAddress((void**)&p_Wqh, g_Wq_h);
    cudaGetSymbolAddress((void**)&p_Wql, g_Wq_l);
    cudaGetSymbolAddress((void**)&p_Wch, g_Wc_h);

    const int SMEM1 = 4 * 20480 + 1024;
    cudaFuncSetAttribute(gemm_all,
                         cudaFuncAttributeMaxDynamicSharedMemorySize, SMEMF);
    cudaFuncSetAttribute(gemm_out,
                         cudaFuncAttributeMaxDynamicSharedMemorySize, SMEM1);

    // All prologue kernels BEFORE gemm_all: the dependent chain
    // gemm_all -> attn -> gemm_out then runs with no serial gaps.
    fold_part_kernel<<<dim3(32, 8), 256>>>(Wf, Wo1, p_part);               // 1
    convert_w3_kernel<<<dim3(256, 3), 256>>>(Wv, p_Wvh, p_Wvl,
                                             Wk, p_Wkh, p_Wkl,
                                             Wq, p_Wqh, p_Wql);            // 2
    fold_reduce_kernel<<<256, 256>>>(p_part, Wf, bo1, bf, p_Wch, p_bc);    // 3
    convert_h_kernel<<<12288, 256>>>(h, p_hh, p_hl);                       // 4 (ncu)
    // fused K+Q+V GEMM (3584 jobs / 296 persistent CTAs)                  // 5
    gemm_all<<<NWORK, 256, SMEMF>>>(
        p_hh, p_hl, p_Wkh, p_Wkl, p_Wqh, p_Wql, p_Wvh,
        bk, bq, bv, p_k1, p_q1, p_Wh1);
    attn_kernel<<<BATCH, 128>>>(p_q1, p_k1, p_Wh1, label, adj, p_f1h);     // 6
    // out GEMM (fp16x1) straight into d_out                               // 7
    gemm_out<<<296, 256, SMEM1>>>(p_f1h, p_Wch, p_bc, out, M_SEL / 128);
}